// round 1
// baseline (speedup 1.0000x reference)
#include <cuda_runtime.h>
#include <cstdint>

// Problem: BoundaryBCELoss
//   N=64, H=W=384. 5 iterations of 3x3 "plus" dilation (conv + clip[0,1]) on
//   hand_mask and object_mask, p = h*o, BCE(target, p) with log clamp -100,
//   output = scalar mean loss (negated mean of t*log p + (1-t)*log(1-p)).
//
// Strategy: fully fused. One block per 32x32 output tile; load 42x42 halo
// tiles of both masks into SMEM, run all 5 dilation iterations in SMEM
// (ping-pong, valid region shrinks 1/iter), compute BCE term, block-reduce,
// atomicAdd scaled partial into d_out. Init kernel zeroes d_out first.

#define IMG_H 384
#define IMG_W 384
#define IMG_N 64
#define TILE  32
#define HALO  5
#define S     (TILE + 2*HALO)   // 42
#define SP    44                // smem row pitch (floats)
#define NTHREADS 256

__global__ void bbl_init_out(float* out) {
    out[0] = 0.0f;
}

__global__ __launch_bounds__(NTHREADS)
void bbl_fused_kernel(const float* __restrict__ hand,
                      const float* __restrict__ obj,
                      const float* __restrict__ targ,
                      float* __restrict__ out)
{
    __shared__ float bh[2][S][SP];
    __shared__ float bo[2][S][SP];
    __shared__ float warpsum[NTHREADS / 32];

    const int tid = threadIdx.x;
    const int n   = blockIdx.z;
    const int tx0 = blockIdx.x * TILE;   // output tile origin
    const int ty0 = blockIdx.y * TILE;
    const int gx0 = tx0 - HALO;          // halo tile origin in image coords
    const int gy0 = ty0 - HALO;
    const size_t base = (size_t)n * IMG_H * IMG_W;

    // ---- load halo tiles (zero-pad outside image) ----
    #pragma unroll
    for (int idx = tid; idx < S * S; idx += NTHREADS) {
        const int r = idx / S;
        const int c = idx - r * S;
        const int y = gy0 + r;
        const int x = gx0 + c;
        float hv = 0.0f, ov = 0.0f;
        if ((unsigned)y < (unsigned)IMG_H && (unsigned)x < (unsigned)IMG_W) {
            const size_t g = base + (size_t)y * IMG_W + x;
            hv = hand[g];
            ov = obj[g];
        }
        bh[0][r][c] = hv;
        bo[0][r][c] = ov;
    }
    __syncthreads();

    // ---- 5 dilation iterations in SMEM, ping-pong, shrinking valid region ----
    int src = 0;
    #pragma unroll
    for (int it = 1; it <= 5; ++it) {
        const int lo   = it;
        const int span = S - 2 * it;     // compile-time constant per iteration
        const int npts = span * span;
        const int dst  = 1 - src;
        for (int idx = tid; idx < npts; idx += NTHREADS) {
            const int r = lo + idx / span;     // div by compile-time const
            const int c = lo + idx % span;
            const float sh = bh[src][r][c-1] + bh[src][r][c] + bh[src][r][c+1]
                           + bh[src][r-1][c] + bh[src][r+1][c];
            const float so = bo[src][r][c-1] + bo[src][r][c] + bo[src][r][c+1]
                           + bo[src][r-1][c] + bo[src][r+1][c];
            bh[dst][r][c] = fminf(sh, 1.0f);
            bo[dst][r][c] = fminf(so, 1.0f);
        }
        __syncthreads();
        src = dst;
    }

    // ---- BCE accumulation over the 32x32 valid output region ----
    float acc = 0.0f;
    #pragma unroll
    for (int idx = tid; idx < TILE * TILE; idx += NTHREADS) {
        const int r = idx / TILE;
        const int c = idx - r * TILE;
        const float h = bh[src][r + HALO][c + HALO];
        const float o = bo[src][r + HALO][c + HALO];
        const float p = h * o;
        // logf(0) = -inf -> clamped to -100, matching reference semantics
        const float lp  = fmaxf(logf(p),        -100.0f);
        const float l1p = fmaxf(logf(1.0f - p), -100.0f);
        const size_t g = base + (size_t)(ty0 + r) * IMG_W + (tx0 + c);
        const float t = targ[g];
        acc += t * lp + (1.0f - t) * l1p;
    }

    // ---- block reduction ----
    #pragma unroll
    for (int off = 16; off > 0; off >>= 1)
        acc += __shfl_down_sync(0xffffffffu, acc, off);
    if ((tid & 31) == 0)
        warpsum[tid >> 5] = acc;
    __syncthreads();
    if (tid == 0) {
        float s = 0.0f;
        #pragma unroll
        for (int w = 0; w < NTHREADS / 32; ++w)
            s += warpsum[w];
        const float scale = -1.0f / ((float)IMG_N * IMG_H * IMG_W);
        atomicAdd(out, s * scale);
    }
}

extern "C" void kernel_launch(void* const* d_in, const int* in_sizes, int n_in,
                              void* d_out, int out_size)
{
    const float* hand = (const float*)d_in[0];
    const float* obj  = (const float*)d_in[1];
    const float* targ = (const float*)d_in[2];
    float* out = (float*)d_out;

    bbl_init_out<<<1, 1>>>(out);

    dim3 grid(IMG_W / TILE, IMG_H / TILE, IMG_N);   // (12, 12, 64)
    bbl_fused_kernel<<<grid, NTHREADS>>>(hand, obj, targ, out);
}

// round 3
// speedup vs baseline: 1.7732x; 1.7732x over previous
#include <cuda_runtime.h>
#include <cstdint>

// BoundaryBCELoss — register-resident fused version.
//
// Key identity: clip(a+b, 0, 1) with a,b >= 0 satisfies
//   min(1, sum_j min(1, a_j)) = min(1, sum_j a_j)
// so the 5 dilate+clamp iterations equal 5 LINEAR 5-point stencil iterations
// followed by a single min(1, .). This lets us pack (hand, obj) into one
// 64-bit f32x2 value and do both masks' stencils with add.rn.f32x2.
//
// Each warp owns an independent tile: 22 output cols (lane=col, 5-col halo
// each side -> 32 lanes) x 32 output rows (42 rows incl halo held in regs).
// Horizontal neighbors via __shfl, vertical via registers. Validity shrinks
// 1/iter so edge-lane / edge-row garbage never reaches the output region.

#define IMG_H 384
#define IMG_W 384
#define IMG_N 64
#define HALO  5
#define TOUT_H 32
#define TOUT_W 22                 // 32 - 2*HALO
#define R      (TOUT_H + 2*HALO)  // 42 rows per thread
#define PX     18                 // ceil(384/22) column panels
#define SY     (IMG_H / TOUT_H)   // 12 row strips
#define WPB    8                  // warps per block
#define NTHREADS 256
#define NTILES (PX * SY * IMG_N)       // 13824
#define NBLOCKS (NTILES / WPB)         // 1728

typedef unsigned long long u64;

__device__ __forceinline__ u64 f2add(u64 a, u64 b) {
    u64 d;
    asm("add.rn.f32x2 %0, %1, %2;" : "=l"(d) : "l"(a), "l"(b));
    return d;
}

__device__ __forceinline__ u64 f2pack(float lo, float hi) {
    return (u64)__float_as_uint(lo) | ((u64)__float_as_uint(hi) << 32);
}

__global__ void bbl_init_out(float* out) { out[0] = 0.0f; }

__global__ __launch_bounds__(NTHREADS)
void bbl_reg_kernel(const float* __restrict__ hand,
                    const float* __restrict__ obj,
                    const float* __restrict__ targ,
                    float* __restrict__ out)
{
    __shared__ float wsum[WPB];

    const int tid  = threadIdx.x;
    const int lane = tid & 31;
    const int warp = tid >> 5;

    const int tile = blockIdx.x * WPB + warp;
    const int n    = tile / (PX * SY);
    const int rm   = tile - n * (PX * SY);
    const int sy   = rm / PX;
    const int px   = rm - sy * PX;

    const int col = px * TOUT_W - HALO + lane;   // this lane's column
    const int y0  = sy * TOUT_H - HALO;          // top row (incl halo)
    const size_t base = (size_t)n * IMG_H * IMG_W;
    const bool col_ok = ((unsigned)col < (unsigned)IMG_W);

    // ---- load 42-row column of both masks, packed (h,o) ----
    u64 v[R];
    #pragma unroll
    for (int r = 0; r < R; ++r) {
        const int y = y0 + r;
        float hv = 0.0f, ov = 0.0f;
        if (col_ok && (unsigned)y < (unsigned)IMG_H) {
            const size_t g = base + (size_t)y * IMG_W + col;
            hv = hand[g];
            ov = obj[g];
        }
        v[r] = f2pack(hv, ov);
    }

    // ---- 5 linear 5-point stencil iterations, all in registers ----
    #pragma unroll 1
    for (int it = 0; it < 5; ++it) {
        u64 above = 0ULL;   // bit pattern of (0.f, 0.f)
        #pragma unroll
        for (int r = 0; r < R; ++r) {
            const u64 cur   = v[r];
            const u64 below = (r < R - 1) ? v[r + 1] : 0ULL;
            const u64 left  = __shfl_up_sync(0xffffffffu, cur, 1);
            const u64 right = __shfl_down_sync(0xffffffffu, cur, 1);
            // s = above + below + left + right + cur   (both masks at once)
            u64 s = f2add(f2add(above, below), f2add(left, right));
            s = f2add(s, cur);
            above = cur;
            v[r]  = s;
        }
    }

    // ---- BCE over the valid 22x32 region of this warp-tile ----
    float acc = 0.0f;
    const bool valid = (lane >= HALO) && (lane < HALO + TOUT_W) && col_ok;
    if (valid) {
        #pragma unroll
        for (int r = HALO; r < HALO + TOUT_H; ++r) {
            const float h = fminf(__uint_as_float((unsigned)(v[r] & 0xffffffffu)), 1.0f);
            const float o = fminf(__uint_as_float((unsigned)(v[r] >> 32)),        1.0f);
            const float p = h * o;
            // __logf(0) = -inf -> clamped to -100 (matches reference clamp)
            const float lp  = fmaxf(__logf(p),        -100.0f);
            const float l1p = fmaxf(__logf(1.0f - p), -100.0f);
            const int y = y0 + r;                 // always in [0, 384)
            const float t = targ[base + (size_t)y * IMG_W + col];
            acc += l1p + t * (lp - l1p);
        }
    }

    // ---- warp then block reduction, one atomic per block ----
    #pragma unroll
    for (int off = 16; off > 0; off >>= 1)
        acc += __shfl_down_sync(0xffffffffu, acc, off);
    if (lane == 0) wsum[warp] = acc;
    __syncthreads();
    if (tid == 0) {
        float s = 0.0f;
        #pragma unroll
        for (int w = 0; w < WPB; ++w) s += wsum[w];
        const float scale = -1.0f / ((float)IMG_N * IMG_H * IMG_W);
        atomicAdd(out, s * scale);
    }
}

extern "C" void kernel_launch(void* const* d_in, const int* in_sizes, int n_in,
                              void* d_out, int out_size)
{
    const float* hand = (const float*)d_in[0];
    const float* obj  = (const float*)d_in[1];
    const float* targ = (const float*)d_in[2];
    float* out = (float*)d_out;

    bbl_init_out<<<1, 1>>>(out);
    bbl_reg_kernel<<<NBLOCKS, NTHREADS>>>(hand, obj, targ, out);
}